// round 13
// baseline (speedup 1.0000x reference)
#include <cuda_runtime.h>
#include <math.h>
#include <stdint.h>

#define THREADS   128
#define IMGS      64                   // images per block, 1 per thread (x2 col-halves)
#define NP4       65                   // float4 stride per v-row (odd -> conflict-free)
#define SMEM_BYTES (14 * NP4 * 16)     // 14560 B

typedef unsigned long long ull;

// W repacked per k: cW2[k*3+0]=((W0,W1),(W2,W3)), [1]=((W4,W5),(W6,W7)), [2]=((W8,W9),pad)
__constant__ ulonglong2 cW2[784 * 3];
__constant__ float      cbias[10];
__device__   ull        g_wp[784 * 6];   // prep scratch

__device__ __forceinline__ void fma2(ull &acc, ull a, ull b) {
    asm("fma.rn.f32x2 %0, %1, %2, %0;" : "+l"(acc) : "l"(a), "l"(b));
}
__device__ __forceinline__ ull pack2(float lo, float hi) {
    ull r; asm("mov.b64 %0, {%1, %2};" : "=l"(r) : "f"(lo), "f"(hi)); return r;
}
__device__ __forceinline__ float2 unpack2(ull v) {
    float lo, hi; asm("mov.b64 {%0, %1}, %2;" : "=f"(lo), "=f"(hi) : "l"(v));
    return make_float2(lo, hi);
}

__global__ void prep_kernel(const float* __restrict__ W) {
    int i = blockIdx.x * blockDim.x + threadIdx.x;   // 0..4703
    if (i < 784 * 6) {
        int k = i / 6, oq = i - 6 * k;
        ull v = 0ull;
        if (oq < 5) {
            uint32_t lo = __float_as_uint(W[(2 * oq)     * 784 + k]);
            uint32_t hi = __float_as_uint(W[(2 * oq + 1) * 784 + k]);
            v = ((ull)hi << 32) | lo;
        }
        g_wp[i] = v;
    }
}

// one patch-row tile, ONE image (slot p), cols CB..CB+6
template<int CB>
__device__ __forceinline__ void compute_tile(const float4* __restrict__ px,
                                             int r, int p, ull* acc)
{
    #pragma unroll
    for (int cc = 0; cc < 7; cc++) {
        const int c  = CB + cc;          // compile-time
        const int vA = c >> 1;
        const int vB = 7 + vA;
        float4 a = px[vA * NP4 + p];     // row 2r pixels 4vA..4vA+3
        float4 b = px[vB * NP4 + p];     // row 2r+1
        float x0, x1, x2, x3;
        if ((c & 1) == 0) { x0 = a.x; x1 = a.y; x2 = b.x; x3 = b.y; }
        else              { x0 = a.z; x1 = a.w; x2 = b.z; x3 = b.w; }
        float e[4];
        e[0] = __cosf(x0);
        e[1] = e[0] * __cosf(x1);
        e[2] = e[1] * __cosf(x2);
        e[3] = e[2] * __cosf(x3);

        const int kb3 = (r * 56 + c * 4) * 3;
        #pragma unroll
        for (int j = 0; j < 4; j++) {
            ulonglong2 w01 = cW2[kb3 + j * 3];       // uniform const (LDCU) loads
            ulonglong2 w23 = cW2[kb3 + j * 3 + 1];
            ulonglong2 w4p = cW2[kb3 + j * 3 + 2];
            ull d = pack2(e[j], e[j]);
            fma2(acc[0], d, w01.x);
            fma2(acc[1], d, w01.y);
            fma2(acc[2], d, w23.x);
            fma2(acc[3], d, w23.y);
            fma2(acc[4], d, w4p.x);
        }
    }
}

__global__ void __launch_bounds__(THREADS, 7)
quanv_kernel(const float* __restrict__ x, float* __restrict__ out)
{
    extern __shared__ float smem[];
    float4* s_px = (float4*)smem;    // [14][NP4] float4, single buffer
    float*  s_mg = smem;             // epilogue merge aliases px buffer

    const int tid   = threadIdx.x;
    const int p     = tid & 63;      // image slot 0..63
    const int chalf = tid >> 6;      // 0: cols 0..6, 1: cols 7..13 (warp-uniform)

    const long imgBase = (long)blockIdx.x * IMGS;
    const float* xg = x + imgBase * 784;

    // granule base (j = tid + 128*it): img = j/14, v = j%14  (64 imgs x 14 v = 896 = 128x7)
    const int v0   = tid % 14;
    const int img0 = tid / 14;
    const int off0 = img0 * 784 + v0 * 4;

    // prefetch tile 0 (7 float4)
    float4 stage[7];
    {
        int v = v0, off = off0;
        #pragma unroll
        for (int it = 0; it < 7; it++) {
            stage[it] = *(const float4*)(xg + off);
            off += 7064; v += 2;                 // j += 128 (img += 9, v += 2)
            if (v >= 14) { v -= 14; off += 728; }
        }
    }

    ull acc[5];
    #pragma unroll
    for (int q = 0; q < 5; q++) acc[q] = 0ull;

    #pragma unroll 1
    for (int r = 0; r < 14; r++) {
        // store staged tile (7 STS.128)
        {
            int v = v0, img = img0;
            #pragma unroll
            for (int it = 0; it < 7; it++) {
                s_px[v * NP4 + img] = stage[it];
                v += 2; img += 9;
                if (v >= 14) { v -= 14; img++; }
            }
        }
        __syncthreads();

        // prefetch next tile — latency hidden behind compute
        if (r < 13) {
            const float* srcT = xg + (r + 1) * 56;
            int v = v0, off = off0;
            #pragma unroll
            for (int it = 0; it < 7; it++) {
                stage[it] = *(const float4*)(srcT + off);
                off += 7064; v += 2;
                if (v >= 14) { v -= 14; off += 728; }
            }
        }

        if (chalf == 0) compute_tile<0>(s_px, r, p, acc);
        else            compute_tile<7>(s_px, r, p, acc);
        __syncthreads();
    }

    // unpack o-pair accumulators
    float sA[10];
    #pragma unroll
    for (int q = 0; q < 5; q++) {
        float2 fa = unpack2(acc[q]);
        sA[2 * q] = fa.x; sA[2 * q + 1] = fa.y;
    }

    // merge the two column-halves via shared (stride 11 -> conflict-free)
    if (chalf == 1) {
        #pragma unroll
        for (int o = 0; o < 10; o++) s_mg[p * 11 + o] = sA[o];
    }
    __syncthreads();

    if (chalf == 0) {
        float l[10];
        float m = -INFINITY;
        #pragma unroll
        for (int o = 0; o < 10; o++) {
            l[o] = sA[o] + s_mg[p * 11 + o] + cbias[o];
            m = fmaxf(m, l[o]);
        }
        float s = 0.f;
        #pragma unroll
        for (int o = 0; o < 10; o++) s += __expf(l[o] - m);
        float lse = m + __logf(s);
        float2* op = (float2*)(out + (imgBase + p) * 10);   // 40B offset: 8B aligned
        #pragma unroll
        for (int q = 0; q < 5; q++)
            op[q] = make_float2(l[2 * q] - lse, l[2 * q + 1] - lse);
    }
}

extern "C" void kernel_launch(void* const* d_in, const int* in_sizes, int n_in,
                              void* d_out, int out_size)
{
    const float* x = (const float*)d_in[0];
    const float* W = (const float*)d_in[1];
    const float* b = (const float*)d_in[2];
    float* out = (float*)d_out;

    prep_kernel<<<19, 256>>>(W);

    void* wp_addr = nullptr;
    cudaGetSymbolAddress(&wp_addr, g_wp);
    cudaMemcpyToSymbolAsync(cW2, wp_addr, 784 * 6 * sizeof(ull), 0,
                            cudaMemcpyDeviceToDevice, 0);
    cudaMemcpyToSymbolAsync(cbias, b, 10 * sizeof(float), 0,
                            cudaMemcpyDeviceToDevice, 0);

    const int B = in_sizes[0] / 784;    // 65536
    const int grid = B / IMGS;          // 1024 (<= 1036 slots at 7 CTAs/SM: one wave)

    cudaFuncSetAttribute(quanv_kernel,
                         cudaFuncAttributeMaxDynamicSharedMemorySize, SMEM_BYTES);
    quanv_kernel<<<grid, THREADS, SMEM_BYTES>>>(x, out);
}